// round 1
// baseline (speedup 1.0000x reference)
#include <cuda_runtime.h>

// ---------------------------------------------------------------------------
// Seq2Seq LSTM (B=256, H=512, TIN=512, TOUT=64, F=64) — persistent kernel.
// All weights live in SMEM (distributed: each of 128 CTAs owns 4 hidden units
// = 16 gate rows of every layer). Cell states stay in registers. Hidden states
// are exchanged through L2 (double-buffered, stcg/ldcg) with a software grid
// barrier between dependent phases. Inner GEMM uses packed fp32x2 FMA.
// ---------------------------------------------------------------------------

namespace {
constexpr int B_    = 256;
constexpr int H_    = 512;
constexpr int F_    = 64;
constexpr int TIN_  = 512;
constexpr int TOUT_ = 64;
constexpr int NCTA  = 128;
constexpr int NTHR  = 256;
constexpr int UPC   = H_ / NCTA;   // hidden units per CTA = 4
constexpr int ROWS  = 4 * UPC;     // gate rows per CTA = 16

// SMEM layout (float offsets). All segment bases are 16B-aligned.
constexpr int OFF_E0I  = 0;                       // [F ][16] enc0 Wih slice (k-major)
constexpr int OFF_E0H  = OFF_E0I + F_ * ROWS;     // [H ][16] enc0 Whh
constexpr int OFF_E1I  = OFF_E0H + H_ * ROWS;     // [H ][16] enc1 Wih
constexpr int OFF_E1H  = OFF_E1I + H_ * ROWS;     // [H ][16] enc1 Whh
constexpr int OFF_D0H  = OFF_E1H + H_ * ROWS;     // [H ][16] dec0 Whh
constexpr int OFF_D1I  = OFF_D0H + H_ * ROWS;     // [H ][16] dec1 Wih
constexpr int OFF_D1H  = OFF_D1I + H_ * ROWS;     // [H ][16] dec1 Whh
constexpr int OFF_D0I  = OFF_D1H + H_ * ROWS;     // [16]     dec0 Wih (K=1)
constexpr int OFF_BIAS = OFF_D0I + ROWS;          // [4][16]  bih+bhh per layer
constexpr int OFF_PW   = OFF_BIAS + 4 * ROWS;     // [4]      proj_W slice
constexpr int SMEM_FLOATS = OFF_PW + UPC;
constexpr int SMEM_BYTES  = SMEM_FLOATS * 4;      // 201,040 B < 227 KB
} // namespace

// ------------------------------ device scratch ------------------------------
__device__ float    d_xT[TIN_ * F_ * B_];   // x transposed to [t][f][b]
__device__ float    d_h0[2][H_ * B_];       // layer-0 hidden, ping-pong, [u][b]
__device__ float    d_h1[2][H_ * B_];       // layer-1 hidden, ping-pong, [u][b]
__device__ float    d_outs[TOUT_ * B_];     // decoder outputs [s][b] (pre-bias)
__device__ unsigned d_count;                // grid barrier counter

// ------------------------------- helpers ------------------------------------
__device__ __forceinline__ unsigned long long ffma2(unsigned long long a,
                                                    unsigned long long b,
                                                    unsigned long long c) {
    unsigned long long d;
    asm("fma.rn.f32x2 %0, %1, %2, %3;" : "=l"(d) : "l"(a), "l"(b), "l"(c));
    return d;
}

__device__ __forceinline__ unsigned long long pack2(float x) {
    unsigned long long d;
    unsigned xi = __float_as_uint(x);
    asm("mov.b64 %0, {%1, %1};" : "=l"(d) : "r"(xi));
    return d;
}

__device__ __forceinline__ void unpack2(unsigned long long v, float& lo, float& hi) {
    unsigned a, b;
    asm("mov.b64 {%0, %1}, %2;" : "=r"(a), "=r"(b) : "l"(v));
    lo = __uint_as_float(a);
    hi = __uint_as_float(b);
}

__device__ __forceinline__ float sigm(float v) { return 1.0f / (1.0f + expf(-v)); }

// Grid barrier: counting, reset to 0 by prep kernel each launch.
__device__ __forceinline__ void gridsync(unsigned& tgt) {
    tgt += NCTA;
    __syncthreads();
    if (threadIdx.x == 0) {
        __threadfence();
        atomicAdd(&d_count, 1u);
        while (*((volatile unsigned*)&d_count) < tgt) {}
        __threadfence();
    }
    __syncthreads();
}

// Load a [ROWS x K] weight slice to SMEM k-major: dst[k*16 + jj] = W[row(jj)][k]
__device__ __forceinline__ void loadW(const float* __restrict__ W, int K,
                                      float* __restrict__ dst, int ub) {
    for (int jj = 0; jj < ROWS; jj++) {
        const float* src = W + ((jj >> 2) * H_ + ub + (jj & 3)) * K;
        for (int k = threadIdx.x; k < K; k += NTHR) dst[k * ROWS + jj] = src[k];
    }
}

// G[b, 0:16] += X[0:K, b-col-major] * W[K x 16]  (W in SMEM, k-major pairs)
template <int K>
__device__ __forceinline__ void gemm_seg(const float* __restrict__ X,
                                         const float* __restrict__ ws,
                                         unsigned long long acc[8], int b) {
#pragma unroll 1
    for (int k0 = 0; k0 < K; k0 += 8) {
        float xv[8];
#pragma unroll
        for (int u = 0; u < 8; u++) xv[u] = __ldcg(X + (k0 + u) * B_ + b);
#pragma unroll
        for (int u = 0; u < 8; u++) {
            unsigned long long xx = pack2(xv[u]);
            const ulonglong2* wp =
                reinterpret_cast<const ulonglong2*>(ws + (k0 + u) * ROWS);
            ulonglong2 w0 = wp[0], w1 = wp[1], w2 = wp[2], w3 = wp[3];
            acc[0] = ffma2(xx, w0.x, acc[0]);
            acc[1] = ffma2(xx, w0.y, acc[1]);
            acc[2] = ffma2(xx, w1.x, acc[2]);
            acc[3] = ffma2(xx, w1.y, acc[3]);
            acc[4] = ffma2(xx, w2.x, acc[4]);
            acc[5] = ffma2(xx, w2.y, acc[5]);
            acc[6] = ffma2(xx, w3.x, acc[6]);
            acc[7] = ffma2(xx, w3.y, acc[7]);
        }
    }
}

__device__ __forceinline__ void init_bias(unsigned long long acc[8],
                                          const float* __restrict__ bs) {
    const ulonglong2* p = reinterpret_cast<const ulonglong2*>(bs);
    ulonglong2 b0 = p[0], b1 = p[1], b2 = p[2], b3 = p[3];
    acc[0] = b0.x; acc[1] = b0.y; acc[2] = b1.x; acc[3] = b1.y;
    acc[4] = b2.x; acc[5] = b2.y; acc[6] = b3.x; acc[7] = b3.y;
}

// LSTM pointwise for the CTA's 4 units (gates in acc, packed pairs, j = q*4+uu)
__device__ __forceinline__ void lstm_point(unsigned long long acc[8],
                                           float c[UPC], float hv[UPC]) {
    float g[16];
#pragma unroll
    for (int p = 0; p < 8; p++) unpack2(acc[p], g[2 * p], g[2 * p + 1]);
#pragma unroll
    for (int uu = 0; uu < UPC; uu++) {
        float ci = sigm(g[4 + uu]) * c[uu] + sigm(g[uu]) * tanhf(g[8 + uu]);
        c[uu] = ci;
        hv[uu] = sigm(g[12 + uu]) * tanhf(ci);
    }
}

// ------------------------------ prep kernel ---------------------------------
__global__ void prep_kernel(const float* __restrict__ x) {
    int gtid = blockIdx.x * blockDim.x + threadIdx.x;
    int stride = gridDim.x * blockDim.x;
    if (gtid == 0) d_count = 0;
    // transpose x[b][t][f] -> xT[t][f][b]
    for (int i = gtid; i < B_ * TIN_ * F_; i += stride) {
        int bb = i / (TIN_ * F_);
        int r = i - bb * TIN_ * F_;
        int t = r >> 6;       // / F_
        int k = r & (F_ - 1); // % F_
        d_xT[(t * F_ + k) * B_ + bb] = x[i];
    }
    for (int i = gtid; i < H_ * B_; i += stride) {
        d_h0[0][i] = 0.0f; d_h0[1][i] = 0.0f;
        d_h1[0][i] = 0.0f; d_h1[1][i] = 0.0f;
    }
    for (int i = gtid; i < TOUT_ * B_; i += stride) d_outs[i] = 0.0f;
}

// --------------------------- persistent kernel ------------------------------
__global__ void __launch_bounds__(NTHR, 1)
lstm_persist(const float* __restrict__ x, float* __restrict__ out,
             const float* __restrict__ e0Wih, const float* __restrict__ e0Whh,
             const float* __restrict__ e0bih, const float* __restrict__ e0bhh,
             const float* __restrict__ e1Wih, const float* __restrict__ e1Whh,
             const float* __restrict__ e1bih, const float* __restrict__ e1bhh,
             const float* __restrict__ d0Wih, const float* __restrict__ d0Whh,
             const float* __restrict__ d0bih, const float* __restrict__ d0bhh,
             const float* __restrict__ d1Wih, const float* __restrict__ d1Whh,
             const float* __restrict__ d1bih, const float* __restrict__ d1bhh,
             const float* __restrict__ projW, const float* __restrict__ projb) {
    extern __shared__ float sm[];
    const int cta = blockIdx.x;
    const int tid = threadIdx.x;
    const int b = tid;            // one batch row per thread
    const int ub = cta * UPC;     // first hidden unit owned by this CTA

    // ---- one-time weight staging to SMEM ----
    loadW(e0Wih, F_, sm + OFF_E0I, ub);
    loadW(e0Whh, H_, sm + OFF_E0H, ub);
    loadW(e1Wih, H_, sm + OFF_E1I, ub);
    loadW(e1Whh, H_, sm + OFF_E1H, ub);
    loadW(d0Whh, H_, sm + OFF_D0H, ub);
    loadW(d1Wih, H_, sm + OFF_D1I, ub);
    loadW(d1Whh, H_, sm + OFF_D1H, ub);
    if (tid < ROWS) {
        int row = (tid >> 2) * H_ + ub + (tid & 3);
        sm[OFF_D0I + tid] = d0Wih[row];  // K = 1
        sm[OFF_BIAS + 0 * ROWS + tid] = e0bih[row] + e0bhh[row];
        sm[OFF_BIAS + 1 * ROWS + tid] = e1bih[row] + e1bhh[row];
        sm[OFF_BIAS + 2 * ROWS + tid] = d0bih[row] + d0bhh[row];
        sm[OFF_BIAS + 3 * ROWS + tid] = d1bih[row] + d1bhh[row];
    }
    if (tid < UPC) sm[OFF_PW + tid] = projW[ub + tid];
    __syncthreads();

    const float pb = __ldg(projb);
    float c0[UPC] = {0.f, 0.f, 0.f, 0.f};
    float c1[UPC] = {0.f, 0.f, 0.f, 0.f};
    float hv[UPC];
    unsigned tgt = 0;
    int cur = 0;

    // ------------------------------- encoder --------------------------------
#pragma unroll 1
    for (int t = 0; t < TIN_; t++) {
        unsigned long long acc[8];
        // cell 0: gates = x_t @ Wih0^T + h0 @ Whh0^T + b
        init_bias(acc, sm + OFF_BIAS + 0 * ROWS);
        gemm_seg<F_>(d_xT + t * F_ * B_, sm + OFF_E0I, acc, b);
        gemm_seg<H_>(d_h0[cur], sm + OFF_E0H, acc, b);
        lstm_point(acc, c0, hv);
#pragma unroll
        for (int uu = 0; uu < UPC; uu++)
            __stcg(&d_h0[cur ^ 1][(ub + uu) * B_ + b], hv[uu]);
        gridsync(tgt);

        // cell 1: gates = h0_new @ Wih1^T + h1 @ Whh1^T + b
        init_bias(acc, sm + OFF_BIAS + 1 * ROWS);
        gemm_seg<H_>(d_h0[cur ^ 1], sm + OFF_E1I, acc, b);
        gemm_seg<H_>(d_h1[cur], sm + OFF_E1H, acc, b);
        lstm_point(acc, c1, hv);
#pragma unroll
        for (int uu = 0; uu < UPC; uu++)
            __stcg(&d_h1[cur ^ 1][(ub + uu) * B_ + b], hv[uu]);
        gridsync(tgt);
        cur ^= 1;
    }

    // ------------------------------- decoder --------------------------------
    float prev = __ldcg(x + b * TIN_ * F_ + (TIN_ - 1) * F_ + (F_ - 1));
#pragma unroll 1
    for (int s = 0; s < TOUT_; s++) {
        unsigned long long acc[8];
        // cell 0: gates = prev * Wih0_col + h0 @ Whh0^T + b   (K_in = 1)
        {
            const ulonglong2* bp =
                reinterpret_cast<const ulonglong2*>(sm + OFF_BIAS + 2 * ROWS);
            const ulonglong2* dp =
                reinterpret_cast<const ulonglong2*>(sm + OFF_D0I);
            ulonglong2 b0 = bp[0], b1 = bp[1], b2 = bp[2], b3 = bp[3];
            ulonglong2 w0 = dp[0], w1 = dp[1], w2 = dp[2], w3 = dp[3];
            unsigned long long pp = pack2(prev);
            acc[0] = ffma2(pp, w0.x, b0.x);
            acc[1] = ffma2(pp, w0.y, b0.y);
            acc[2] = ffma2(pp, w1.x, b1.x);
            acc[3] = ffma2(pp, w1.y, b1.y);
            acc[4] = ffma2(pp, w2.x, b2.x);
            acc[5] = ffma2(pp, w2.y, b2.y);
            acc[6] = ffma2(pp, w3.x, b3.x);
            acc[7] = ffma2(pp, w3.y, b3.y);
        }
        gemm_seg<H_>(d_h0[cur], sm + OFF_D0H, acc, b);
        lstm_point(acc, c0, hv);
#pragma unroll
        for (int uu = 0; uu < UPC; uu++)
            __stcg(&d_h0[cur ^ 1][(ub + uu) * B_ + b], hv[uu]);
        gridsync(tgt);

        // cell 1 + projection partial
        init_bias(acc, sm + OFF_BIAS + 3 * ROWS);
        gemm_seg<H_>(d_h0[cur ^ 1], sm + OFF_D1I, acc, b);
        gemm_seg<H_>(d_h1[cur], sm + OFF_D1H, acc, b);
        lstm_point(acc, c1, hv);
        float part = 0.0f;
#pragma unroll
        for (int uu = 0; uu < UPC; uu++) {
            __stcg(&d_h1[cur ^ 1][(ub + uu) * B_ + b], hv[uu]);
            part += hv[uu] * sm[OFF_PW + uu];
        }
        atomicAdd(&d_outs[s * B_ + b], part);
        gridsync(tgt);

        prev = __ldcg(&d_outs[s * B_ + b]) + pb;
        cur ^= 1;
    }

    // ------------------------------- output ---------------------------------
    // out[b][s] = outs[s][b] + proj_b  (16384 elements over 32768 threads)
    int idx = cta * NTHR + tid;
    if (idx < B_ * TOUT_) {
        int ob = idx >> 6;
        int os = idx & (TOUT_ - 1);
        out[idx] = __ldcg(&d_outs[os * B_ + ob]) + pb;
    }
}

// ------------------------------ entry point ---------------------------------
extern "C" void kernel_launch(void* const* d_in, const int* in_sizes, int n_in,
                              void* d_out, int out_size) {
    const float* x     = (const float*)d_in[0];
    // d_in[1] = y (only defines TOUT, values unused)
    const float* e0Wih = (const float*)d_in[2];
    const float* e0Whh = (const float*)d_in[3];
    const float* e0bih = (const float*)d_in[4];
    const float* e0bhh = (const float*)d_in[5];
    const float* e1Wih = (const float*)d_in[6];
    const float* e1Whh = (const float*)d_in[7];
    const float* e1bih = (const float*)d_in[8];
    const float* e1bhh = (const float*)d_in[9];
    const float* d0Wih = (const float*)d_in[10];
    const float* d0Whh = (const float*)d_in[11];
    const float* d0bih = (const float*)d_in[12];
    const float* d0bhh = (const float*)d_in[13];
    const float* d1Wih = (const float*)d_in[14];
    const float* d1Whh = (const float*)d_in[15];
    const float* d1bih = (const float*)d_in[16];
    const float* d1bhh = (const float*)d_in[17];
    const float* projW = (const float*)d_in[18];
    const float* projb = (const float*)d_in[19];
    float* out = (float*)d_out;

    cudaFuncSetAttribute(lstm_persist,
                         cudaFuncAttributeMaxDynamicSharedMemorySize, SMEM_BYTES);

    prep_kernel<<<2048, 256>>>(x);
    lstm_persist<<<NCTA, NTHR, SMEM_BYTES>>>(
        x, out,
        e0Wih, e0Whh, e0bih, e0bhh,
        e1Wih, e1Whh, e1bih, e1bhh,
        d0Wih, d0Whh, d0bih, d0bhh,
        d1Wih, d1Whh, d1bih, d1bhh,
        projW, projb);
}

// round 2
// speedup vs baseline: 1.0404x; 1.0404x over previous
#include <cuda_runtime.h>

// ---------------------------------------------------------------------------
// Seq2Seq LSTM (B=256, H=512, TIN=512, TOUT=64, F=64) — persistent kernel.
// All weights live in SMEM (distributed: each of 128 CTAs owns 4 hidden units
// = 16 gate rows of every layer). Cell states stay in registers. Hidden states
// are exchanged through L2 (double-buffered, stcg/ldcg) with a software grid
// barrier between dependent phases. Inner GEMM uses packed fp32x2 FMA.
// ---------------------------------------------------------------------------

namespace {
constexpr int B_    = 256;
constexpr int H_    = 512;
constexpr int F_    = 64;
constexpr int TIN_  = 512;
constexpr int TOUT_ = 64;
constexpr int NCTA  = 128;
constexpr int NTHR  = 256;
constexpr int UPC   = H_ / NCTA;   // hidden units per CTA = 4
constexpr int ROWS  = 4 * UPC;     // gate rows per CTA = 16

// SMEM layout (float offsets). All segment bases are 16B-aligned.
constexpr int OFF_E0I  = 0;                       // [F ][16] enc0 Wih slice (k-major)
constexpr int OFF_E0H  = OFF_E0I + F_ * ROWS;     // [H ][16] enc0 Whh
constexpr int OFF_E1I  = OFF_E0H + H_ * ROWS;     // [H ][16] enc1 Wih
constexpr int OFF_E1H  = OFF_E1I + H_ * ROWS;     // [H ][16] enc1 Whh
constexpr int OFF_D0H  = OFF_E1H + H_ * ROWS;     // [H ][16] dec0 Whh
constexpr int OFF_D1I  = OFF_D0H + H_ * ROWS;     // [H ][16] dec1 Wih
constexpr int OFF_D1H  = OFF_D1I + H_ * ROWS;     // [H ][16] dec1 Whh
constexpr int OFF_D0I  = OFF_D1H + H_ * ROWS;     // [16]     dec0 Wih (K=1)
constexpr int OFF_BIAS = OFF_D0I + ROWS;          // [4][16]  bih+bhh per layer
constexpr int OFF_PW   = OFF_BIAS + 4 * ROWS;     // [4]      proj_W slice
constexpr int SMEM_FLOATS = OFF_PW + UPC;
constexpr int SMEM_BYTES  = SMEM_FLOATS * 4;      // 201,040 B < 227 KB
} // namespace

// ------------------------------ device scratch ------------------------------
__device__ float    d_xT[TIN_ * F_ * B_];   // x transposed to [t][f][b]
__device__ float    d_h0[2][H_ * B_];       // layer-0 hidden, ping-pong, [u][b]
__device__ float    d_h1[2][H_ * B_];       // layer-1 hidden, ping-pong, [u][b]
__device__ float    d_outs[TOUT_ * B_];     // decoder outputs [s][b] (pre-bias)
__device__ unsigned d_count;                // grid barrier counter

// ------------------------------- helpers ------------------------------------
__device__ __forceinline__ unsigned long long ffma2(unsigned long long a,
                                                    unsigned long long b,
                                                    unsigned long long c) {
    unsigned long long d;
    asm("fma.rn.f32x2 %0, %1, %2, %3;" : "=l"(d) : "l"(a), "l"(b), "l"(c));
    return d;
}

__device__ __forceinline__ unsigned long long pack2(float x) {
    unsigned long long d;
    unsigned xi = __float_as_uint(x);
    asm("mov.b64 %0, {%1, %1};" : "=l"(d) : "r"(xi));
    return d;
}

__device__ __forceinline__ void unpack2(unsigned long long v, float& lo, float& hi) {
    unsigned a, b;
    asm("mov.b64 {%0, %1}, %2;" : "=r"(a), "=r"(b) : "l"(v));
    lo = __uint_as_float(a);
    hi = __uint_as_float(b);
}

__device__ __forceinline__ float sigm(float v) { return 1.0f / (1.0f + expf(-v)); }

// Grid barrier: counting, reset to 0 by prep kernel each launch.
__device__ __forceinline__ void gridsync(unsigned& tgt) {
    tgt += NCTA;
    __syncthreads();
    if (threadIdx.x == 0) {
        __threadfence();
        atomicAdd(&d_count, 1u);
        while (*((volatile unsigned*)&d_count) < tgt) {}
        __threadfence();
    }
    __syncthreads();
}

// Load a [ROWS x K] weight slice to SMEM k-major: dst[k*16 + jj] = W[row(jj)][k]
__device__ __forceinline__ void loadW(const float* __restrict__ W, int K,
                                      float* __restrict__ dst, int ub) {
    for (int jj = 0; jj < ROWS; jj++) {
        const float* src = W + ((jj >> 2) * H_ + ub + (jj & 3)) * K;
        for (int k = threadIdx.x; k < K; k += NTHR) dst[k * ROWS + jj] = src[k];
    }
}

// G[b, 0:16] += X[0:K, b-col-major] * W[K x 16]  (W in SMEM, k-major pairs)
template <int K>
__device__ __forceinline__ void gemm_seg(const float* __restrict__ X,
                                         const float* __restrict__ ws,
                                         unsigned long long acc[8], int b) {
#pragma unroll 1
    for (int k0 = 0; k0 < K; k0 += 8) {
        float xv[8];
#pragma unroll
        for (int u = 0; u < 8; u++) xv[u] = __ldcg(X + (k0 + u) * B_ + b);
#pragma unroll
        for (int u = 0; u < 8; u++) {
            unsigned long long xx = pack2(xv[u]);
            const ulonglong2* wp =
                reinterpret_cast<const ulonglong2*>(ws + (k0 + u) * ROWS);
            ulonglong2 w0 = wp[0], w1 = wp[1], w2 = wp[2], w3 = wp[3];
            acc[0] = ffma2(xx, w0.x, acc[0]);
            acc[1] = ffma2(xx, w0.y, acc[1]);
            acc[2] = ffma2(xx, w1.x, acc[2]);
            acc[3] = ffma2(xx, w1.y, acc[3]);
            acc[4] = ffma2(xx, w2.x, acc[4]);
            acc[5] = ffma2(xx, w2.y, acc[5]);
            acc[6] = ffma2(xx, w3.x, acc[6]);
            acc[7] = ffma2(xx, w3.y, acc[7]);
        }
    }
}

__device__ __forceinline__ void init_bias(unsigned long long acc[8],
                                          const float* __restrict__ bs) {
    const ulonglong2* p = reinterpret_cast<const ulonglong2*>(bs);
    ulonglong2 b0 = p[0], b1 = p[1], b2 = p[2], b3 = p[3];
    acc[0] = b0.x; acc[1] = b0.y; acc[2] = b1.x; acc[3] = b1.y;
    acc[4] = b2.x; acc[5] = b2.y; acc[6] = b3.x; acc[7] = b3.y;
}

// LSTM pointwise for the CTA's 4 units (gates in acc, packed pairs, j = q*4+uu)
__device__ __forceinline__ void lstm_point(unsigned long long acc[8],
                                           float c[UPC], float hv[UPC]) {
    float g[16];
#pragma unroll
    for (int p = 0; p < 8; p++) unpack2(acc[p], g[2 * p], g[2 * p + 1]);
#pragma unroll
    for (int uu = 0; uu < UPC; uu++) {
        float ci = sigm(g[4 + uu]) * c[uu] + sigm(g[uu]) * tanhf(g[8 + uu]);
        c[uu] = ci;
        hv[uu] = sigm(g[12 + uu]) * tanhf(ci);
    }
}

// ------------------------------ prep kernel ---------------------------------
__global__ void prep_kernel(const float* __restrict__ x) {
    int gtid = blockIdx.x * blockDim.x + threadIdx.x;
    int stride = gridDim.x * blockDim.x;
    if (gtid == 0) d_count = 0;
    // transpose x[b][t][f] -> xT[t][f][b]
    for (int i = gtid; i < B_ * TIN_ * F_; i += stride) {
        int bb = i / (TIN_ * F_);
        int r = i - bb * TIN_ * F_;
        int t = r >> 6;       // / F_
        int k = r & (F_ - 1); // % F_
        d_xT[(t * F_ + k) * B_ + bb] = x[i];
    }
    for (int i = gtid; i < H_ * B_; i += stride) {
        d_h0[0][i] = 0.0f; d_h0[1][i] = 0.0f;
        d_h1[0][i] = 0.0f; d_h1[1][i] = 0.0f;
    }
    for (int i = gtid; i < TOUT_ * B_; i += stride) d_outs[i] = 0.0f;
}

// --------------------------- persistent kernel ------------------------------
__global__ void __launch_bounds__(NTHR, 1)
lstm_persist(const float* __restrict__ x, float* __restrict__ out,
             const float* __restrict__ e0Wih, const float* __restrict__ e0Whh,
             const float* __restrict__ e0bih, const float* __restrict__ e0bhh,
             const float* __restrict__ e1Wih, const float* __restrict__ e1Whh,
             const float* __restrict__ e1bih, const float* __restrict__ e1bhh,
             const float* __restrict__ d0Wih, const float* __restrict__ d0Whh,
             const float* __restrict__ d0bih, const float* __restrict__ d0bhh,
             const float* __restrict__ d1Wih, const float* __restrict__ d1Whh,
             const float* __restrict__ d1bih, const float* __restrict__ d1bhh,
             const float* __restrict__ projW, const float* __restrict__ projb) {
    extern __shared__ float sm[];
    const int cta = blockIdx.x;
    const int tid = threadIdx.x;
    const int b = tid;            // one batch row per thread
    const int ub = cta * UPC;     // first hidden unit owned by this CTA

    // ---- one-time weight staging to SMEM ----
    loadW(e0Wih, F_, sm + OFF_E0I, ub);
    loadW(e0Whh, H_, sm + OFF_E0H, ub);
    loadW(e1Wih, H_, sm + OFF_E1I, ub);
    loadW(e1Whh, H_, sm + OFF_E1H, ub);
    loadW(d0Whh, H_, sm + OFF_D0H, ub);
    loadW(d1Wih, H_, sm + OFF_D1I, ub);
    loadW(d1Whh, H_, sm + OFF_D1H, ub);
    if (tid < ROWS) {
        int row = (tid >> 2) * H_ + ub + (tid & 3);
        sm[OFF_D0I + tid] = d0Wih[row];  // K = 1
        sm[OFF_BIAS + 0 * ROWS + tid] = e0bih[row] + e0bhh[row];
        sm[OFF_BIAS + 1 * ROWS + tid] = e1bih[row] + e1bhh[row];
        sm[OFF_BIAS + 2 * ROWS + tid] = d0bih[row] + d0bhh[row];
        sm[OFF_BIAS + 3 * ROWS + tid] = d1bih[row] + d1bhh[row];
    }
    if (tid < UPC) sm[OFF_PW + tid] = projW[ub + tid];
    __syncthreads();

    const float pb = __ldg(projb);
    float c0[UPC] = {0.f, 0.f, 0.f, 0.f};
    float c1[UPC] = {0.f, 0.f, 0.f, 0.f};
    float hv[UPC];
    unsigned tgt = 0;
    int cur = 0;

    // ------------------------------- encoder --------------------------------
#pragma unroll 1
    for (int t = 0; t < TIN_; t++) {
        unsigned long long acc[8];
        // cell 0: gates = x_t @ Wih0^T + h0 @ Whh0^T + b
        init_bias(acc, sm + OFF_BIAS + 0 * ROWS);
        gemm_seg<F_>(d_xT + t * F_ * B_, sm + OFF_E0I, acc, b);
        gemm_seg<H_>(d_h0[cur], sm + OFF_E0H, acc, b);
        lstm_point(acc, c0, hv);
#pragma unroll
        for (int uu = 0; uu < UPC; uu++)
            __stcg(&d_h0[cur ^ 1][(ub + uu) * B_ + b], hv[uu]);
        gridsync(tgt);

        // cell 1: gates = h0_new @ Wih1^T + h1 @ Whh1^T + b
        init_bias(acc, sm + OFF_BIAS + 1 * ROWS);
        gemm_seg<H_>(d_h0[cur ^ 1], sm + OFF_E1I, acc, b);
        gemm_seg<H_>(d_h1[cur], sm + OFF_E1H, acc, b);
        lstm_point(acc, c1, hv);
#pragma unroll
        for (int uu = 0; uu < UPC; uu++)
            __stcg(&d_h1[cur ^ 1][(ub + uu) * B_ + b], hv[uu]);
        gridsync(tgt);
        cur ^= 1;
    }

    // ------------------------------- decoder --------------------------------
    float prev = __ldcg(x + b * TIN_ * F_ + (TIN_ - 1) * F_ + (F_ - 1));
#pragma unroll 1
    for (int s = 0; s < TOUT_; s++) {
        unsigned long long acc[8];
        // cell 0: gates = prev * Wih0_col + h0 @ Whh0^T + b   (K_in = 1)
        {
            const ulonglong2* bp =
                reinterpret_cast<const ulonglong2*>(sm + OFF_BIAS + 2 * ROWS);
            const ulonglong2* dp =
                reinterpret_cast<const ulonglong2*>(sm + OFF_D0I);
            ulonglong2 b0 = bp[0], b1 = bp[1], b2 = bp[2], b3 = bp[3];
            ulonglong2 w0 = dp[0], w1 = dp[1], w2 = dp[2], w3 = dp[3];
            unsigned long long pp = pack2(prev);
            acc[0] = ffma2(pp, w0.x, b0.x);
            acc[1] = ffma2(pp, w0.y, b0.y);
            acc[2] = ffma2(pp, w1.x, b1.x);
            acc[3] = ffma2(pp, w1.y, b1.y);
            acc[4] = ffma2(pp, w2.x, b2.x);
            acc[5] = ffma2(pp, w2.y, b2.y);
            acc[6] = ffma2(pp, w3.x, b3.x);
            acc[7] = ffma2(pp, w3.y, b3.y);
        }
        gemm_seg<H_>(d_h0[cur], sm + OFF_D0H, acc, b);
        lstm_point(acc, c0, hv);
#pragma unroll
        for (int uu = 0; uu < UPC; uu++)
            __stcg(&d_h0[cur ^ 1][(ub + uu) * B_ + b], hv[uu]);
        gridsync(tgt);

        // cell 1 + projection partial
        init_bias(acc, sm + OFF_BIAS + 3 * ROWS);
        gemm_seg<H_>(d_h0[cur ^ 1], sm + OFF_D1I, acc, b);
        gemm_seg<H_>(d_h1[cur], sm + OFF_D1H, acc, b);
        lstm_point(acc, c1, hv);
        float part = 0.0f;
#pragma unroll
        for (int uu = 0; uu < UPC; uu++) {
            __stcg(&d_h1[cur ^ 1][(ub + uu) * B_ + b], hv[uu]);
            part += hv[uu] * sm[OFF_PW + uu];
        }
        atomicAdd(&d_outs[s * B_ + b], part);
        gridsync(tgt);

        prev = __ldcg(&d_outs[s * B_ + b]) + pb;
        cur ^= 1;
    }

    // ------------------------------- output ---------------------------------
    // out[b][s] = outs[s][b] + proj_b  (16384 elements over 32768 threads)
    int idx = cta * NTHR + tid;
    if (idx < B_ * TOUT_) {
        int ob = idx >> 6;
        int os = idx & (TOUT_ - 1);
        out[idx] = __ldcg(&d_outs[os * B_ + ob]) + pb;
    }
}

// ------------------------------ entry point ---------------------------------
extern "C" void kernel_launch(void* const* d_in, const int* in_sizes, int n_in,
                              void* d_out, int out_size) {
    const float* x     = (const float*)d_in[0];
    // d_in[1] = y (only defines TOUT, values unused)
    const float* e0Wih = (const float*)d_in[2];
    const float* e0Whh = (const float*)d_in[3];
    const float* e0bih = (const float*)d_in[4];
    const float* e0bhh = (const float*)d_in[5];
    const float* e1Wih = (const float*)d_in[6];
    const float* e1Whh = (const float*)d_in[7];
    const float* e1bih = (const float*)d_in[8];
    const float* e1bhh = (const float*)d_in[9];
    const float* d0Wih = (const float*)d_in[10];
    const float* d0Whh = (const float*)d_in[11];
    const float* d0bih = (const float*)d_in[12];
    const float* d0bhh = (const float*)d_in[13];
    const float* d1Wih = (const float*)d_in[14];
    const float* d1Whh = (const float*)d_in[15];
    const float* d1bih = (const float*)d_in[16];
    const float* d1bhh = (const float*)d_in[17];
    const float* projW = (const float*)d_in[18];
    const float* projb = (const float*)d_in[19];
    float* out = (float*)d_out;

    cudaFuncSetAttribute(lstm_persist,
                         cudaFuncAttributeMaxDynamicSharedMemorySize, SMEM_BYTES);

    prep_kernel<<<2048, 256>>>(x);
    lstm_persist<<<NCTA, NTHR, SMEM_BYTES>>>(
        x, out,
        e0Wih, e0Whh, e0bih, e0bhh,
        e1Wih, e1Whh, e1bih, e1bhh,
        d0Wih, d0Whh, d0bih, d0bhh,
        d1Wih, d1Whh, d1bih, d1bhh,
        projW, projb);
}

// round 3
// speedup vs baseline: 3.0542x; 2.9357x over previous
#include <cuda_runtime.h>
#include <cuda_fp16.h>

// ---------------------------------------------------------------------------
// Seq2Seq LSTM (B=256, H=512, TIN=512, TOUT=64) — persistent kernel v2.
// Tensor-core microkernel: mma.sync.m16n8k16 (f16 in, fp32 accum).
// 128 CTAs x 512 thr. CTA owns 16 gate cols (4 hidden units) of every layer;
// weights packed once into SMEM as per-lane MMA B-fragments (f16). X (x_t/h)
// streams from L2 in f16 [b][k] row-major with a per-16 k-permutation so each
// lane's A-fragment halves are one LDG.64. Cell states in regs. Software grid
// barrier between dependent phases. Deterministic projection feedback.
// ---------------------------------------------------------------------------

namespace {
constexpr int B_ = 256, H_ = 512, F_ = 64, TIN_ = 512, TOUT_ = 64;
constexpr int NCTA = 128, NTHR = 512;
constexpr int FSEG(int K) { return (K / 16) * 64; }  // uint2 slots per segment
constexpr int FE0I = 0;
constexpr int FE0H = FE0I + FSEG(F_);
constexpr int FE1I = FE0H + FSEG(H_);
constexpr int FE1H = FE1I + FSEG(H_);
constexpr int FD0H = FE1H + FSEG(H_);
constexpr int FD1I = FD0H + FSEG(H_);
constexpr int FD1H = FD1I + FSEG(H_);
constexpr int FRAG_TOT = FD1H + FSEG(H_);           // 12544 uint2 = 100352 B
constexpr int SF_BIAS = 0, SF_WD0 = 64, SF_PW = 80, SF_PREV = 96;
constexpr int SF_TOT = SF_PREV + B_;
constexpr int SMEM_BYTES = FRAG_TOT * 8 + SF_TOT * 4;  // ~101.8 KB
}  // namespace

// ------------------------------ device scratch ------------------------------
__device__ __half   d_xT[TIN_ * B_ * F_];  // x as [t][b][f-permuted], f16
__device__ __half   d_h0[2][B_ * H_];      // layer-0 h, [b][u-permuted]
__device__ __half   d_h1[2][B_ * H_];      // layer-1 h
__device__ float    d_prev0[B_];           // x[:, -1, -1]
__device__ float    d_part[B_ * NCTA];     // projection partials [b][cta]
__device__ unsigned d_count;               // grid barrier counter

// ------------------------------- helpers ------------------------------------
__device__ __forceinline__ void mma16816(float* d, unsigned a0, unsigned a1,
                                         unsigned a2, unsigned a3,
                                         unsigned b0, unsigned b1) {
    asm volatile(
        "mma.sync.aligned.m16n8k16.row.col.f32.f16.f16.f32 "
        "{%0,%1,%2,%3}, {%4,%5,%6,%7}, {%8,%9}, {%0,%1,%2,%3};\n"
        : "+f"(d[0]), "+f"(d[1]), "+f"(d[2]), "+f"(d[3])
        : "r"(a0), "r"(a1), "r"(a2), "r"(a3), "r"(b0), "r"(b1));
}
__device__ __forceinline__ float sigmf_(float x) { return 1.0f / (1.0f + __expf(-x)); }
__device__ __forceinline__ float tanhf_(float x) {
    float t = __expf(2.0f * x);
    return __fdividef(t - 1.0f, t + 1.0f);
}
// logical k (within 16) -> physical slot: {2c,2c+1,2c+8,2c+9} -> {4c..4c+3}
__device__ __forceinline__ int permv(int v) {
    return 4 * ((v >> 1) & 3) + (v & 1) + 2 * ((v >> 3) & 1);
}
__device__ __forceinline__ void gridsync(unsigned& tgt) {
    tgt += NCTA;
    __syncthreads();
    if (threadIdx.x == 0) {
        __threadfence();
        atomicAdd(&d_count, 1u);
        while (*(volatile unsigned*)&d_count < tgt) {}
        __threadfence();
    }
    __syncthreads();
}

// Pack CTA's 16 gate cols of W[4H x K] into per-lane B fragments (f16).
__device__ void packW(const float* __restrict__ W, int K,
                      uint2* __restrict__ dst, int ub) {
    int nslots = (K / 16) * 64;
    for (int s = threadIdx.x; s < nslots; s += NTHR) {
        int l = s & 31, nt = (s >> 5) & 1, kt = s >> 6;
        int g = l >> 2, c = l & 3;
        int j = nt * 8 + g;
        const float* row = W + ((j >> 2) * H_ + ub + (j & 3)) * K + kt * 16;
        __half2 h0 = __floats2half2_rn(row[2 * c], row[2 * c + 1]);
        __half2 h1 = __floats2half2_rn(row[2 * c + 8], row[2 * c + 9]);
        uint2 o;
        o.x = *(unsigned*)&h0;
        o.y = *(unsigned*)&h1;
        dst[s] = o;
    }
}

// d0/d1 += X[r0..r0+15, :16*KT] @ Wseg. X row-major f16 stride S (permuted k).
template <int KT>
__device__ __forceinline__ void gemmSeg(const __half* __restrict__ X, int S,
                                        int r0, int c,
                                        const uint2* __restrict__ f, int lane,
                                        float* d0, float* d1) {
    const __half* pa = X + r0 * S + 4 * c;
    const __half* pb = pa + 8 * S;
    const uint2* pf = f + lane;
#pragma unroll 8
    for (int kt = 0; kt < KT; kt++) {
        uint2 ra = __ldcg((const uint2*)(pa + kt * 16));
        uint2 rb = __ldcg((const uint2*)(pb + kt * 16));
        uint2 w0 = pf[kt * 64];
        uint2 w1 = pf[kt * 64 + 32];
        mma16816(d0, ra.x, rb.x, ra.y, rb.y, w0.x, w0.y);
        mma16816(d1, ra.x, rb.x, ra.y, rb.y, w1.x, w1.y);
    }
}

// LSTM pointwise. d0 = i|f gates, d1 = g|o gates; lanes c<2 own units 2c,2c+1.
__device__ __forceinline__ void cellEpi(float* d0, float* d1, float* cst,
                                        float* hv) {
    float ff[4], oo[4];
#pragma unroll
    for (int q = 0; q < 4; q++) {
        ff[q] = __shfl_xor_sync(0xffffffffu, d0[q], 2);
        oo[q] = __shfl_xor_sync(0xffffffffu, d1[q], 2);
    }
#pragma unroll
    for (int q = 0; q < 4; q++) {
        float cn = sigmf_(ff[q]) * cst[q] + sigmf_(d0[q]) * tanhf_(d1[q]);
        cst[q] = cn;
        hv[q] = sigmf_(oo[q]) * tanhf_(cn);
    }
}

// Store 4 h values (units u0,u0+1 at rows r0,r0+8) into permuted f16 layout.
__device__ __forceinline__ void storeH(__half* hb, int r0, int c, int u0,
                                       const float* hv) {
    if (c < 2) {
        __half2 lo = __floats2half2_rn(hv[0], hv[1]);
        __half2 hi = __floats2half2_rn(hv[2], hv[3]);
        int off = (u0 & ~15) + 4 * ((u0 >> 1) & 3) + 2 * ((u0 >> 3) & 1);
        __stcg((unsigned*)(hb + r0 * H_ + off), *(unsigned*)&lo);
        __stcg((unsigned*)(hb + (r0 + 8) * H_ + off), *(unsigned*)&hi);
    }
}

// ------------------------------ prep kernel ---------------------------------
__global__ void prep_kernel(const float* __restrict__ x) {
    int gt = blockIdx.x * blockDim.x + threadIdx.x;
    int stride = gridDim.x * blockDim.x;
    if (gt == 0) d_count = 0;
    for (int i = gt; i < TIN_ * B_ * F_; i += stride) {
        int f = i & 63, b = (i >> 6) & 255, t = i >> 14;
        int fp = (f & ~15) + permv(f & 15);
        d_xT[(t * B_ + b) * F_ + fp] = __float2half(x[(b << 15) | (t << 6) | f]);
    }
    __half z = __float2half(0.0f);
    for (int i = gt; i < B_ * H_; i += stride) {
        d_h0[0][i] = z; d_h0[1][i] = z;
        d_h1[0][i] = z; d_h1[1][i] = z;
    }
    if (gt < B_)
        d_prev0[gt] = x[gt * (TIN_ * F_) + (TIN_ - 1) * F_ + (F_ - 1)];
}

// --------------------------- persistent kernel ------------------------------
__global__ void __launch_bounds__(NTHR, 1)
lstm_persist(const float* __restrict__ x, float* __restrict__ out,
             const float* __restrict__ e0Wih, const float* __restrict__ e0Whh,
             const float* __restrict__ e0bih, const float* __restrict__ e0bhh,
             const float* __restrict__ e1Wih, const float* __restrict__ e1Whh,
             const float* __restrict__ e1bih, const float* __restrict__ e1bhh,
             const float* __restrict__ d0Wih, const float* __restrict__ d0Whh,
             const float* __restrict__ d0bih, const float* __restrict__ d0bhh,
             const float* __restrict__ d1Wih, const float* __restrict__ d1Whh,
             const float* __restrict__ d1bih, const float* __restrict__ d1bhh,
             const float* __restrict__ projW, const float* __restrict__ projb) {
    extern __shared__ unsigned smraw[];
    uint2* frag = (uint2*)smraw;
    float* sf = (float*)(smraw + FRAG_TOT * 2);
    float* sBias = sf + SF_BIAS;
    float* sWd0 = sf + SF_WD0;
    float* sPw = sf + SF_PW;
    float* sPrev = sf + SF_PREV;

    const int cta = blockIdx.x, tid = threadIdx.x;
    const int lane = tid & 31, warp = tid >> 5;
    const int g = lane >> 2, c = lane & 3;
    const int r0 = warp * 16 + g;
    const int ub = cta * 4;

    // ---- one-time weight packing ----
    packW(e0Wih, F_, frag + FE0I, ub);
    packW(e0Whh, H_, frag + FE0H, ub);
    packW(e1Wih, H_, frag + FE1I, ub);
    packW(e1Whh, H_, frag + FE1H, ub);
    packW(d0Whh, H_, frag + FD0H, ub);
    packW(d1Wih, H_, frag + FD1I, ub);
    packW(d1Whh, H_, frag + FD1H, ub);
    if (tid < 16) {
        int r = (tid >> 2) * H_ + ub + (tid & 3);
        sBias[0 * 16 + tid] = e0bih[r] + e0bhh[r];
        sBias[1 * 16 + tid] = e1bih[r] + e1bhh[r];
        sBias[2 * 16 + tid] = d0bih[r] + d0bhh[r];
        sBias[3 * 16 + tid] = d1bih[r] + d1bhh[r];
        sWd0[tid] = d0Wih[r];
    }
    if (tid < 4) sPw[tid] = projW[ub + tid];
    __syncthreads();

    float bA[4][2], bB[4][2];
#pragma unroll
    for (int ty = 0; ty < 4; ty++) {
        bA[ty][0] = sBias[ty * 16 + 2 * c];
        bA[ty][1] = sBias[ty * 16 + 2 * c + 1];
        bB[ty][0] = sBias[ty * 16 + 8 + 2 * c];
        bB[ty][1] = sBias[ty * 16 + 8 + 2 * c + 1];
    }
    const float wdA0 = sWd0[2 * c], wdA1 = sWd0[2 * c + 1];
    const float wdB0 = sWd0[8 + 2 * c], wdB1 = sWd0[8 + 2 * c + 1];
    const float pw0 = sPw[(2 * c) & 3], pw1 = sPw[(2 * c + 1) & 3];
    const float pb = projb[0];
    const int u0 = ub + 2 * c;

    float cst0[4] = {0.f, 0.f, 0.f, 0.f};
    float cst1[4] = {0.f, 0.f, 0.f, 0.f};
    float d0[4], d1[4], hv[4];
    unsigned tgt = 0;
    int cur = 0;

    // ------------------------------- encoder --------------------------------
#pragma unroll 1
    for (int t = 0; t < TIN_; t++) {
        // cell 0: x_t @ Wih0^T + h0 @ Whh0^T + b
        d0[0] = bA[0][0]; d0[1] = bA[0][1]; d0[2] = bA[0][0]; d0[3] = bA[0][1];
        d1[0] = bB[0][0]; d1[1] = bB[0][1]; d1[2] = bB[0][0]; d1[3] = bB[0][1];
        gemmSeg<F_ / 16>(d_xT + t * B_ * F_, F_, r0, c, frag + FE0I, lane, d0, d1);
        gemmSeg<H_ / 16>(d_h0[cur], H_, r0, c, frag + FE0H, lane, d0, d1);
        cellEpi(d0, d1, cst0, hv);
        storeH(d_h0[cur ^ 1], r0, c, u0, hv);
        gridsync(tgt);

        // cell 1: h0_new @ Wih1^T + h1 @ Whh1^T + b
        d0[0] = bA[1][0]; d0[1] = bA[1][1]; d0[2] = bA[1][0]; d0[3] = bA[1][1];
        d1[0] = bB[1][0]; d1[1] = bB[1][1]; d1[2] = bB[1][0]; d1[3] = bB[1][1];
        gemmSeg<H_ / 16>(d_h0[cur ^ 1], H_, r0, c, frag + FE1I, lane, d0, d1);
        gemmSeg<H_ / 16>(d_h1[cur], H_, r0, c, frag + FE1H, lane, d0, d1);
        cellEpi(d0, d1, cst1, hv);
        storeH(d_h1[cur ^ 1], r0, c, u0, hv);
        gridsync(tgt);
        cur ^= 1;
    }

    // ------------------------------- decoder --------------------------------
    if (tid < B_) sPrev[tid] = d_prev0[tid];
    __syncthreads();

#pragma unroll 1
    for (int s = 0; s < TOUT_; s++) {
        // cell 0: prev * Wih0_col + h0 @ Whh0^T + b (K_in = 1)
        float pg = sPrev[r0], ph = sPrev[r0 + 8];
        d0[0] = fmaf(pg, wdA0, bA[2][0]); d0[1] = fmaf(pg, wdA1, bA[2][1]);
        d0[2] = fmaf(ph, wdA0, bA[2][0]); d0[3] = fmaf(ph, wdA1, bA[2][1]);
        d1[0] = fmaf(pg, wdB0, bB[2][0]); d1[1] = fmaf(pg, wdB1, bB[2][1]);
        d1[2] = fmaf(ph, wdB0, bB[2][0]); d1[3] = fmaf(ph, wdB1, bB[2][1]);
        gemmSeg<H_ / 16>(d_h0[cur], H_, r0, c, frag + FD0H, lane, d0, d1);
        cellEpi(d0, d1, cst0, hv);
        storeH(d_h0[cur ^ 1], r0, c, u0, hv);
        gridsync(tgt);

        // cell 1 + projection partial
        d0[0] = bA[3][0]; d0[1] = bA[3][1]; d0[2] = bA[3][0]; d0[3] = bA[3][1];
        d1[0] = bB[3][0]; d1[1] = bB[3][1]; d1[2] = bB[3][0]; d1[3] = bB[3][1];
        gemmSeg<H_ / 16>(d_h0[cur ^ 1], H_, r0, c, frag + FD1I, lane, d0, d1);
        gemmSeg<H_ / 16>(d_h1[cur], H_, r0, c, frag + FD1H, lane, d0, d1);
        cellEpi(d0, d1, cst1, hv);
        storeH(d_h1[cur ^ 1], r0, c, u0, hv);
        float qg = hv[0] * pw0 + hv[1] * pw1;
        float qh = hv[2] * pw0 + hv[3] * pw1;
        qg += __shfl_xor_sync(0xffffffffu, qg, 1);
        qh += __shfl_xor_sync(0xffffffffu, qh, 1);
        if (c == 0) {
            __stcg(&d_part[r0 * NCTA + cta], qg);
            __stcg(&d_part[(r0 + 8) * NCTA + cta], qh);
        }
        gridsync(tgt);

        // deterministic fixed-order reduction of 128 partials per batch row
        if (tid < B_) {
            const float* pp = d_part + tid * NCTA;
            float s0 = 0.f, s1 = 0.f, s2 = 0.f, s3 = 0.f;
#pragma unroll
            for (int k = 0; k < NCTA; k += 4) {
                s0 += __ldcg(pp + k);
                s1 += __ldcg(pp + k + 1);
                s2 += __ldcg(pp + k + 2);
                s3 += __ldcg(pp + k + 3);
            }
            float v = ((s0 + s1) + (s2 + s3)) + pb;
            sPrev[tid] = v;
            if (cta == 0) out[tid * TOUT_ + s] = v;
        }
        __syncthreads();
        cur ^= 1;
    }
}

// ------------------------------ entry point ---------------------------------
extern "C" void kernel_launch(void* const* d_in, const int* in_sizes, int n_in,
                              void* d_out, int out_size) {
    const float* x     = (const float*)d_in[0];
    const float* e0Wih = (const float*)d_in[2];
    const float* e0Whh = (const float*)d_in[3];
    const float* e0bih = (const float*)d_in[4];
    const float* e0bhh = (const float*)d_in[5];
    const float* e1Wih = (const float*)d_in[6];
    const float* e1Whh = (const float*)d_in[7];
    const float* e1bih = (const float*)d_in[8];
    const float* e1bhh = (const float*)d_in[9];
    const float* d0Wih = (const float*)d_in[10];
    const float* d0Whh = (const float*)d_in[11];
    const float* d0bih = (const float*)d_in[12];
    const float* d0bhh = (const float*)d_in[13];
    const float* d1Wih = (const float*)d_in[14];
    const float* d1Whh = (const float*)d_in[15];
    const float* d1bih = (const float*)d_in[16];
    const float* d1bhh = (const float*)d_in[17];
    const float* projW = (const float*)d_in[18];
    const float* projb = (const float*)d_in[19];
    float* out = (float*)d_out;

    cudaFuncSetAttribute(lstm_persist,
                         cudaFuncAttributeMaxDynamicSharedMemorySize, SMEM_BYTES);

    prep_kernel<<<2048, 256>>>(x);
    lstm_persist<<<NCTA, NTHR, SMEM_BYTES>>>(
        x, out,
        e0Wih, e0Whh, e0bih, e0bhh,
        e1Wih, e1Whh, e1bih, e1bhh,
        d0Wih, d0Whh, d0bih, d0bhh,
        d1Wih, d1Whh, d1bih, d1bhh,
        projW, projb);
}